// round 11
// baseline (speedup 1.0000x reference)
#include <cuda_runtime.h>
#include <math.h>

#define SR          44100.0
#define N_SAMPLES   131072
#define N_GRAINS    512
#define GRAIN_N     4096
#define BATCH       32
#define R_TILE      2048      /* output samples per synth block */
#define N_TILES     64        /* N_SAMPLES / R_TILE */
#define LOG2_F0_MIN 8.0f
#define LOG2_F0_MAX 13.0f
#define TYP_SLOPE   14.35546875f  /* 44100/(12*256) */
#define PI_F        3.14159265358979323846f
#define TWO_PI_F    6.28318530717958647692f
#define WT_N        1028      /* float4 entries per shifted window table */

// ---- scratch (no allocations allowed) ----
__device__ double g_a[BATCH];                // gamma*ln2/SR
__device__ double g_pref[BATCH];             // exp(-2048a)
__device__ double g_denom[BATCH];            // expm1(a)  (0 => a==0 path)
__device__ float  g_rhof[BATCH];             // (float)exp(a)
__device__ double g_c8[BATCH * 256];         // expm1(8a*tid)/denom  (or 8*tid)
__device__ double g_R8[BATCH * 256];         // exp(8a*tid)
__device__ double g_f0s[BATCH * N_GRAINS];   // f0/SR per grain
__device__ float  g_coeff[BATCH * N_GRAINS]; // amp_norm / sqrt(f0)
__device__ float4 g_WT[4 * WT_N];            // shifted zero-padded window, 4-packed
__device__ double g_sum[BATCH];              // ||x||^2 accumulator

// ============================================================
// Kernel 1: prep. 32 blocks x 512 threads (block b = batch b).
//  S(t) = pref*expm1(a(t+1))/denom extends the reference cumsum
//  closed form to all integer t (grain factor f0/SR split off).
// ============================================================
__global__ void prep_kernel(const float* __restrict__ theta_d,
                            const float* __restrict__ theta_s,
                            const float* __restrict__ log2_f0_u) {
    const int b   = blockIdx.x;
    const int tid = threadIdx.x;

    const float d     = theta_d[b];
    const float slope = theta_s[b] * 2.0f - 1.0f;
    const float gamma_f = tanf(0.95f * slope * (PI_F * 0.5f)) * TYP_SLOPE * 0.25f;
    const double a = (double)gamma_f * 0.6931471805599453 / SR;

    if (tid == 0) {
        g_a[b]     = a;
        g_pref[b]  = (a == 0.0) ? 1.0 : exp(-2048.0 * a);
        g_denom[b] = (a == 0.0) ? 0.0 : expm1(a);
        g_rhof[b]  = (float)exp(a);
        g_sum[b]   = 0.0;
    }
    if (tid < 256) {
        if (a == 0.0) {
            g_c8[b * 256 + tid] = 8.0 * (double)tid;
            g_R8[b * 256 + tid] = 1.0;
        } else {
            const double denom = expm1(a);
            g_c8[b * 256 + tid] = expm1(8.0 * a * (double)tid) / denom;
            g_R8[b * 256 + tid] = exp(8.0 * a * (double)tid);
        }
    }

    // ---- per-grain quantities ----
    const float offset = 0.25f * d + 0.75f * d * d;
    const float so0  = (1.0f - d) * (float)N_GRAINS * (0.0f - offset);
    const float amp0 = 1.0f / (1.0f + expf(2.0f * so0));   // max amp (g=0)

    for (int g = tid; g < N_GRAINS; g += 512) {
        const int idx = b * N_GRAINS + g;
        const float u  = log2_f0_u[idx];
        const float f0 = exp2f(u * (LOG2_F0_MAX - LOG2_F0_MIN) + LOG2_F0_MIN);
        const float so = (1.0f - d) * (float)N_GRAINS * ((float)g / (float)N_GRAINS - offset);
        const float amp = 1.0f / (1.0f + expf(2.0f * so));
        g_coeff[idx] = (amp / amp0) / sqrtf(f0);
        g_f0s[idx]   = (double)f0 / SR;
    }

    // ---- shifted window tables: WT[h][jj] covers t = 4*(jj-2)+h+i ----
    if (b < 4) {
        const int h = b;
        for (int jj = tid; jj < WT_N; jj += 512) {
            float4 wv;
            float* wp = (float*)&wv;
            #pragma unroll
            for (int i = 0; i < 4; i++) {
                const int t = 4 * (jj - 2) + h + i;
                if (t >= 0 && t < GRAIN_N) {
                    const float w = sinpif((float)t / (float)GRAIN_N);
                    wp[i] = w * w;
                } else wp[i] = 0.0f;
            }
            g_WT[h * WT_N + jj] = wv;
        }
    }
}

// ============================================================
// Kernel 2: gather synth + fused norm. 2048 blocks x 256 threads.
// Block (b, tile) owns out[b][r0 : r0+2048); thread owns 8
// contiguous samples in registers. Scans the batch's 512 grains,
// accumulating overlaps. No atomics on out, no memset, output
// written exactly once.
// ============================================================
__global__ void __launch_bounds__(256)
synth_kernel(const int* __restrict__ onsets, float* __restrict__ out) {
    const int bid  = blockIdx.x;
    const int b    = bid >> 6;
    const int tile = bid & 63;
    const int r0   = tile * R_TILE;
    const int tid  = threadIdx.x;

    const double a     = g_a[b];
    const double pref  = g_pref[b];
    const double denom = g_denom[b];
    const float  rho   = g_rhof[b];
    const double Ct    = g_c8[b * 256 + tid];   // offset 8*tid from T
    const double Rt    = g_R8[b * 256 + tid];   // rho^(8*tid)

    const int*    __restrict__ ons   = onsets  + (b << 9);
    const double* __restrict__ f0row = g_f0s   + (b << 9);
    const float*  __restrict__ crow  = g_coeff + (b << 9);

    float acc[8];
    #pragma unroll
    for (int i = 0; i < 8; i++) acc[i] = 0.0f;

    for (int g = 0; g < N_GRAINS; g++) {
        const int onset = __ldg(ons + g);
        const int T = r0 - onset;                       // grain-relative tile start
        if (T <= -R_TILE || T >= GRAIN_N) continue;     // block-uniform reject

        const int t0 = T + 8 * tid;                     // this thread's grain offset
        if (t0 > -8 && t0 < GRAIN_N) {
            const double f0s   = __ldg(f0row + g);
            const float  coeff = __ldg(crow + g);

            // cancellation-free seed at T (|a*(T+1)| < 3 here)
            const double S_T = (denom == 0.0) ? (double)(T + 1)
                             : pref * expm1(a * (double)(T + 1)) / denom;
            const double D_T = fma(denom, S_T, pref);   // = pref*exp(a(T+1))

            const double S  = fma(D_T, Ct, S_T);        // S(t0)
            const double P  = f0s * S;                  // phase in cycles
            const double fr = P - rint(P);              // [-0.5, 0.5]
            float w   = (float)fr * TWO_PI_F;
            float dlt = (float)(f0s * D_T * Rt) * TWO_PI_F;  // rad/sample at t0

            // window: two aligned float4 loads from the h-shifted table
            const int h  = t0 & 3;                      // == T & 3 (8*tid % 4 == 0)
            const int jj = ((t0 - h) >> 2) + 2;
            const float4* __restrict__ wt = g_WT + h * WT_N;
            const float4 w40 = __ldg(wt + jj);
            const float4 w41 = __ldg(wt + jj + 1);

            acc[0] = fmaf(__sinf(w) * coeff, w40.x, acc[0]); w += dlt; dlt *= rho;
            acc[1] = fmaf(__sinf(w) * coeff, w40.y, acc[1]); w += dlt; dlt *= rho;
            acc[2] = fmaf(__sinf(w) * coeff, w40.z, acc[2]); w += dlt; dlt *= rho;
            acc[3] = fmaf(__sinf(w) * coeff, w40.w, acc[3]); w += dlt; dlt *= rho;
            acc[4] = fmaf(__sinf(w) * coeff, w41.x, acc[4]); w += dlt; dlt *= rho;
            acc[5] = fmaf(__sinf(w) * coeff, w41.y, acc[5]); w += dlt; dlt *= rho;
            acc[6] = fmaf(__sinf(w) * coeff, w41.z, acc[6]); w += dlt; dlt *= rho;
            acc[7] = fmaf(__sinf(w) * coeff, w41.w, acc[7]);
        }
    }

    // write out (once, coalesced, 32B-aligned per thread)
    float4* __restrict__ o4 =
        (float4*)(out + (size_t)b * N_SAMPLES + r0 + 8 * tid);
    o4[0] = make_float4(acc[0], acc[1], acc[2], acc[3]);
    o4[1] = make_float4(acc[4], acc[5], acc[6], acc[7]);

    // fused norm^2: block partial -> one double atomic per block
    float ss = 0.0f;
    #pragma unroll
    for (int i = 0; i < 8; i++) ss = fmaf(acc[i], acc[i], ss);
    __shared__ float sh[8];
    for (int off = 16; off > 0; off >>= 1)
        ss += __shfl_down_sync(0xFFFFFFFFu, ss, off);
    if ((tid & 31) == 0) sh[tid >> 5] = ss;
    __syncthreads();
    if (tid < 8) {
        ss = sh[tid];
        for (int off = 4; off > 0; off >>= 1)
            ss += __shfl_down_sync(0xFFu, ss, off);
        if (tid == 0) atomicAdd(&g_sum[b], (double)ss);
    }
}

// ============================================================
// Kernel 3: scale by 1/norm. 2048 blocks x 256 threads, 2 float4.
// ============================================================
__global__ void __launch_bounds__(256)
scale_kernel(float4* __restrict__ out4) {
    const int b    = blockIdx.x >> 6;               // 64 blocks per batch
    const int base = blockIdx.x * 512 + threadIdx.x;

    const float inv = rsqrtf((float)g_sum[b]);

    #pragma unroll
    for (int k = 0; k < 2; k++) {
        float4 v = out4[base + 256 * k];
        v.x *= inv; v.y *= inv; v.z *= inv; v.w *= inv;
        out4[base + 256 * k] = v;
    }
}

extern "C" void kernel_launch(void* const* d_in, const int* in_sizes, int n_in,
                              void* d_out, int out_size) {
    const float* theta_d = (const float*)d_in[0];
    const float* theta_s = (const float*)d_in[1];
    const float* u       = (const float*)d_in[2];
    const int*   onsets  = (const int*)d_in[3];
    float* out = (float*)d_out;

    prep_kernel<<<BATCH, 512>>>(theta_d, theta_s, u);

    synth_kernel<<<BATCH * N_TILES, 256>>>(onsets, out);

    scale_kernel<<<2048, 256>>>((float4*)out);
}

// round 12
// speedup vs baseline: 1.5277x; 1.5277x over previous
#include <cuda_runtime.h>
#include <math.h>

#define SR          44100.0
#define N_SAMPLES   131072
#define N_GRAINS    512
#define GRAIN_N     4096
#define BATCH       32
#define R_TILE      2048      /* output samples per synth block */
#define N_TILES     64        /* N_SAMPLES / R_TILE */
#define TAB_N       6144      /* S/D table entries: T in [-2048, 4096) */
#define LOG2_F0_MIN 8.0f
#define LOG2_F0_MAX 13.0f
#define TYP_SLOPE   14.35546875f  /* 44100/(12*256) */
#define PI_F        3.14159265358979323846f
#define TWO_PI_F    6.28318530717958647692f
#define WT_N        1028      /* float4 entries per shifted window table */

// ---- scratch (no allocations allowed) ----
__device__ double2 g_SD[BATCH * TAB_N];      // {S(T), D(T)} per batch, idx = T+2048
__device__ float  g_rhof[BATCH];             // (float)exp(a)
__device__ double g_c8[BATCH * 256];         // (rho^(8k)-1)/(rho-1)
__device__ double g_R8[BATCH * 256];         // rho^(8k)
__device__ double g_f0s[BATCH * N_GRAINS];   // f0/SR per grain
__device__ float  g_coeff[BATCH * N_GRAINS]; // amp_norm / sqrt(f0)
__device__ float4 g_WT[4 * WT_N];            // shifted zero-padded window, 4-packed
__device__ double g_sum[BATCH];              // ||x||^2 accumulator

// ============================================================
// Kernel 1: prep. grid (32, 14) x 512 threads.
//  part 0      : scalars, c8/R8 tables, per-grain quantities
//  part 1..12  : S/D table chunk (512 entries each)
//  part 13     : shifted window tables (b < 4 only)
//  S(T) = pref*expm1(a(T+1))/denom extends the reference cumsum
//  closed form to all integer T; D(T) = S(T+1)-S(T) = pref*e^{a(T+1)}.
// ============================================================
__global__ void prep_kernel(const float* __restrict__ theta_d,
                            const float* __restrict__ theta_s,
                            const float* __restrict__ log2_f0_u) {
    const int b    = blockIdx.x;
    const int part = blockIdx.y;
    const int tid  = threadIdx.x;

    const float d     = theta_d[b];
    const float slope = theta_s[b] * 2.0f - 1.0f;
    const float gamma_f = tanf(0.95f * slope * (PI_F * 0.5f)) * TYP_SLOPE * 0.25f;
    const double a = (double)gamma_f * 0.6931471805599453 / SR;

    if (part == 0) {
        if (tid == 0) {
            g_rhof[b] = (float)exp(a);
            g_sum[b]  = 0.0;
        }
        if (tid < 256) {
            if (a == 0.0) {
                g_c8[b * 256 + tid] = 8.0 * (double)tid;
                g_R8[b * 256 + tid] = 1.0;
            } else {
                g_c8[b * 256 + tid] = expm1(8.0 * a * (double)tid) / expm1(a);
                g_R8[b * 256 + tid] = exp(8.0 * a * (double)tid);
            }
        }
        // ---- per-grain quantities ----
        const float offset = 0.25f * d + 0.75f * d * d;
        const float so0  = (1.0f - d) * (float)N_GRAINS * (0.0f - offset);
        const float amp0 = 1.0f / (1.0f + expf(2.0f * so0));   // max amp (g=0)
        const int idx = b * N_GRAINS + tid;                    // 512 grains, 512 threads
        const float u  = log2_f0_u[idx];
        const float f0 = exp2f(u * (LOG2_F0_MAX - LOG2_F0_MIN) + LOG2_F0_MIN);
        const float so = (1.0f - d) * (float)N_GRAINS * ((float)tid / (float)N_GRAINS - offset);
        const float amp = 1.0f / (1.0f + expf(2.0f * so));
        g_coeff[idx] = (amp / amp0) / sqrtf(f0);
        g_f0s[idx]   = (double)f0 / SR;
    } else if (part <= 12) {
        const int e = (part - 1) * 512 + tid;   // table index 0..6143
        const int T = e - 2048;
        double S, D;
        if (a == 0.0) {
            S = (double)(T + 1);
            D = 1.0;
        } else {
            const double pref  = exp(-2048.0 * a);
            const double denom = expm1(a);
            S = pref * expm1(a * (double)(T + 1)) / denom;
            D = fma(denom, S, pref);            // = pref*exp(a(T+1))
        }
        g_SD[b * TAB_N + e] = make_double2(S, D);
    } else {
        // ---- shifted window tables: WT[h][jj] covers t = 4*(jj-2)+h+i ----
        if (b < 4) {
            const int h = b;
            for (int jj = tid; jj < WT_N; jj += 512) {
                float4 wv;
                float* wp = (float*)&wv;
                #pragma unroll
                for (int i = 0; i < 4; i++) {
                    const int t = 4 * (jj - 2) + h + i;
                    if (t >= 0 && t < GRAIN_N) {
                        const float w = sinpif((float)t / (float)GRAIN_N);
                        wp[i] = w * w;
                    } else wp[i] = 0.0f;
                }
                g_WT[h * WT_N + jj] = wv;
            }
        }
    }
}

// ============================================================
// Kernel 2: gather synth + fused norm. 2048 blocks x 256 threads.
// Block (b, tile) owns out[b][r0 : r0+2048); thread owns 8
// contiguous samples in registers. Scans the batch's 512 grains;
// per accepted grain: ONE uniform double2 table load for (S_T, D_T),
// then per-thread fma-only DP seed + fp32 phase walk. No atomics
// on out, no memset, output written exactly once.
// ============================================================
__global__ void __launch_bounds__(256)
synth_kernel(const int* __restrict__ onsets, float* __restrict__ out) {
    const int bid  = blockIdx.x;
    const int b    = bid >> 6;
    const int tile = bid & 63;
    const int r0   = tile * R_TILE;
    const int tid  = threadIdx.x;

    const float  rho = g_rhof[b];
    const double Ct  = g_c8[b * 256 + tid];   // offset 8*tid from T
    const double Rt  = g_R8[b * 256 + tid];   // rho^(8*tid)

    const int*     __restrict__ ons   = onsets + (b << 9);
    const double*  __restrict__ f0row = g_f0s  + (b << 9);
    const float*   __restrict__ crow  = g_coeff + (b << 9);
    const double2* __restrict__ sdtab = g_SD + b * TAB_N + 2048;

    float acc[8];
    #pragma unroll
    for (int i = 0; i < 8; i++) acc[i] = 0.0f;

    for (int g = 0; g < N_GRAINS; g++) {
        const int onset = __ldg(ons + g);
        const int T = r0 - onset;                       // grain-relative tile start
        if (T <= -R_TILE || T >= GRAIN_N) continue;     // block-uniform reject

        const int t0 = T + 8 * tid;                     // this thread's grain offset
        if (t0 > -8 && t0 < GRAIN_N) {
            const double2 sd = __ldg(sdtab + T);        // uniform, L2-resident
            const double f0s   = __ldg(f0row + g);
            const float  coeff = __ldg(crow + g);

            const double S  = fma(sd.y, Ct, sd.x);      // S(t0)
            const double P  = f0s * S;                  // phase in cycles
            const double fr = P - rint(P);              // [-0.5, 0.5]
            float w   = (float)fr * TWO_PI_F;
            float dlt = (float)(f0s * sd.y * Rt) * TWO_PI_F;  // rad/sample at t0

            // window: two aligned float4 loads from the h-shifted table
            const int h  = t0 & 3;                      // == T & 3 (8*tid % 4 == 0)
            const int jj = ((t0 - h) >> 2) + 2;
            const float4* __restrict__ wt = g_WT + h * WT_N;
            const float4 w40 = __ldg(wt + jj);
            const float4 w41 = __ldg(wt + jj + 1);

            acc[0] = fmaf(__sinf(w) * coeff, w40.x, acc[0]); w += dlt; dlt *= rho;
            acc[1] = fmaf(__sinf(w) * coeff, w40.y, acc[1]); w += dlt; dlt *= rho;
            acc[2] = fmaf(__sinf(w) * coeff, w40.z, acc[2]); w += dlt; dlt *= rho;
            acc[3] = fmaf(__sinf(w) * coeff, w40.w, acc[3]); w += dlt; dlt *= rho;
            acc[4] = fmaf(__sinf(w) * coeff, w41.x, acc[4]); w += dlt; dlt *= rho;
            acc[5] = fmaf(__sinf(w) * coeff, w41.y, acc[5]); w += dlt; dlt *= rho;
            acc[6] = fmaf(__sinf(w) * coeff, w41.z, acc[6]); w += dlt; dlt *= rho;
            acc[7] = fmaf(__sinf(w) * coeff, w41.w, acc[7]);
        }
    }

    // write out (once, coalesced, 32B-aligned per thread)
    float4* __restrict__ o4 =
        (float4*)(out + (size_t)b * N_SAMPLES + r0 + 8 * tid);
    o4[0] = make_float4(acc[0], acc[1], acc[2], acc[3]);
    o4[1] = make_float4(acc[4], acc[5], acc[6], acc[7]);

    // fused norm^2: block partial -> one double atomic per block
    float ss = 0.0f;
    #pragma unroll
    for (int i = 0; i < 8; i++) ss = fmaf(acc[i], acc[i], ss);
    __shared__ float sh[8];
    for (int off = 16; off > 0; off >>= 1)
        ss += __shfl_down_sync(0xFFFFFFFFu, ss, off);
    if ((tid & 31) == 0) sh[tid >> 5] = ss;
    __syncthreads();
    if (tid < 8) {
        ss = sh[tid];
        for (int off = 4; off > 0; off >>= 1)
            ss += __shfl_down_sync(0xFFu, ss, off);
        if (tid == 0) atomicAdd(&g_sum[b], (double)ss);
    }
}

// ============================================================
// Kernel 3: scale by 1/norm. 2048 blocks x 256 threads, 2 float4.
// ============================================================
__global__ void __launch_bounds__(256)
scale_kernel(float4* __restrict__ out4) {
    const int b    = blockIdx.x >> 6;               // 64 blocks per batch
    const int base = blockIdx.x * 512 + threadIdx.x;

    const float inv = rsqrtf((float)g_sum[b]);

    #pragma unroll
    for (int k = 0; k < 2; k++) {
        float4 v = out4[base + 256 * k];
        v.x *= inv; v.y *= inv; v.z *= inv; v.w *= inv;
        out4[base + 256 * k] = v;
    }
}

extern "C" void kernel_launch(void* const* d_in, const int* in_sizes, int n_in,
                              void* d_out, int out_size) {
    const float* theta_d = (const float*)d_in[0];
    const float* theta_s = (const float*)d_in[1];
    const float* u       = (const float*)d_in[2];
    const int*   onsets  = (const int*)d_in[3];
    float* out = (float*)d_out;

    dim3 pgrid(BATCH, 14);
    prep_kernel<<<pgrid, 512>>>(theta_d, theta_s, u);

    synth_kernel<<<BATCH * N_TILES, 256>>>(onsets, out);

    scale_kernel<<<2048, 256>>>((float4*)out);
}

// round 13
// speedup vs baseline: 4.4932x; 2.9412x over previous
#include <cuda_runtime.h>
#include <math.h>

#define SR          44100.0
#define N_SAMPLES   131072
#define N_GRAINS    512
#define GRAIN_N     4096
#define BATCH       32
#define R_TILE      2048      /* output samples per synth block */
#define N_TILES     64        /* N_SAMPLES / R_TILE */
#define TAB_N       6144      /* S/D table entries: T in [-2048, 4096) */
#define LOG2_F0_MIN 8.0f
#define LOG2_F0_MAX 13.0f
#define TYP_SLOPE   14.35546875f  /* 44100/(12*256) */
#define PI_F        3.14159265358979323846f
#define TWO_PI_F    6.28318530717958647692f
#define WT_N        1028      /* float4 entries per shifted window table */

// ---- scratch (no allocations allowed) ----
__device__ double2 g_SD[BATCH * TAB_N];      // {S(T), D(T)} per batch, idx = T+2048
__device__ float  g_rhof[BATCH];             // (float)exp(a)
__device__ double g_c8[BATCH * 256];         // (rho^(8k)-1)/(rho-1)
__device__ double g_R8[BATCH * 256];         // rho^(8k)
__device__ double g_f0s[BATCH * N_GRAINS];   // f0/SR per grain
__device__ float  g_coeff[BATCH * N_GRAINS]; // amp_norm / sqrt(f0)
__device__ float4 g_WT[4 * WT_N];            // shifted zero-padded window, 4-packed
__device__ double g_sum[BATCH];              // ||x||^2 accumulator

// ============================================================
// Kernel 1: prep. grid (32, 14) x 512 threads.  (unchanged R12)
// ============================================================
__global__ void prep_kernel(const float* __restrict__ theta_d,
                            const float* __restrict__ theta_s,
                            const float* __restrict__ log2_f0_u) {
    const int b    = blockIdx.x;
    const int part = blockIdx.y;
    const int tid  = threadIdx.x;

    const float d     = theta_d[b];
    const float slope = theta_s[b] * 2.0f - 1.0f;
    const float gamma_f = tanf(0.95f * slope * (PI_F * 0.5f)) * TYP_SLOPE * 0.25f;
    const double a = (double)gamma_f * 0.6931471805599453 / SR;

    if (part == 0) {
        if (tid == 0) {
            g_rhof[b] = (float)exp(a);
            g_sum[b]  = 0.0;
        }
        if (tid < 256) {
            if (a == 0.0) {
                g_c8[b * 256 + tid] = 8.0 * (double)tid;
                g_R8[b * 256 + tid] = 1.0;
            } else {
                g_c8[b * 256 + tid] = expm1(8.0 * a * (double)tid) / expm1(a);
                g_R8[b * 256 + tid] = exp(8.0 * a * (double)tid);
            }
        }
        const float offset = 0.25f * d + 0.75f * d * d;
        const float so0  = (1.0f - d) * (float)N_GRAINS * (0.0f - offset);
        const float amp0 = 1.0f / (1.0f + expf(2.0f * so0));
        const int idx = b * N_GRAINS + tid;
        const float u  = log2_f0_u[idx];
        const float f0 = exp2f(u * (LOG2_F0_MAX - LOG2_F0_MIN) + LOG2_F0_MIN);
        const float so = (1.0f - d) * (float)N_GRAINS * ((float)tid / (float)N_GRAINS - offset);
        const float amp = 1.0f / (1.0f + expf(2.0f * so));
        g_coeff[idx] = (amp / amp0) / sqrtf(f0);
        g_f0s[idx]   = (double)f0 / SR;
    } else if (part <= 12) {
        const int e = (part - 1) * 512 + tid;   // table index 0..6143
        const int T = e - 2048;
        double S, D;
        if (a == 0.0) {
            S = (double)(T + 1);
            D = 1.0;
        } else {
            const double pref  = exp(-2048.0 * a);
            const double denom = expm1(a);
            S = pref * expm1(a * (double)(T + 1)) / denom;
            D = fma(denom, S, pref);            // = pref*exp(a(T+1))
        }
        g_SD[b * TAB_N + e] = make_double2(S, D);
    } else {
        if (b < 4) {
            const int h = b;
            for (int jj = tid; jj < WT_N; jj += 512) {
                float4 wv;
                float* wp = (float*)&wv;
                #pragma unroll
                for (int i = 0; i < 4; i++) {
                    const int t = 4 * (jj - 2) + h + i;
                    if (t >= 0 && t < GRAIN_N) {
                        const float w = sinpif((float)t / (float)GRAIN_N);
                        wp[i] = w * w;
                    } else wp[i] = 0.0f;
                }
                g_WT[h * WT_N + jj] = wv;
            }
        }
    }
}

// ============================================================
// Kernel 2: gather synth + fused norm. 2048 blocks x 256 threads.
// Phase A: ordered parallel compaction of the 512-grain list into
//          smem (ballot + per-warp prefix; ~25 survivors, grain
//          order preserved -> accumulation order identical to R12).
// Phase B: loop over survivors only; body unchanged from R12.
// ============================================================
__global__ void __launch_bounds__(256)
synth_kernel(const int* __restrict__ onsets, float* __restrict__ out) {
    __shared__ int   sT[512];
    __shared__ short sG[512];
    __shared__ int   wcnt[8];

    const int bid  = blockIdx.x;
    const int b    = bid >> 6;
    const int tile = bid & 63;
    const int r0   = tile * R_TILE;
    const int tid  = threadIdx.x;
    const int wid  = tid >> 5, lane = tid & 31;

    const int* __restrict__ ons = onsets + (b << 9);

    // ---- Phase A: ordered compaction (2 phases of 256 grains) ----
    int total = 0;
    #pragma unroll
    for (int p = 0; p < 2; p++) {
        const int g = (p << 8) + tid;
        const int T = r0 - __ldg(ons + g);
        const bool ok = (T > -R_TILE) && (T < GRAIN_N);
        const unsigned m = __ballot_sync(0xFFFFFFFFu, ok);
        if (lane == 0) wcnt[wid] = __popc(m);
        __syncthreads();
        int base = total, all = 0;
        #pragma unroll
        for (int w = 0; w < 8; w++) {
            if (w < wid) base += wcnt[w];
            all += wcnt[w];
        }
        if (ok) {
            const int pos = base + __popc(m & ((1u << lane) - 1));
            sT[pos] = T;
            sG[pos] = (short)g;
        }
        total += all;
        __syncthreads();
    }

    const float  rho = g_rhof[b];
    const double Ct  = g_c8[b * 256 + tid];   // offset 8*tid from T
    const double Rt  = g_R8[b * 256 + tid];   // rho^(8*tid)

    const double*  __restrict__ f0row = g_f0s   + (b << 9);
    const float*   __restrict__ crow  = g_coeff + (b << 9);
    const double2* __restrict__ sdtab = g_SD + b * TAB_N + 2048;

    float acc[8];
    #pragma unroll
    for (int i = 0; i < 8; i++) acc[i] = 0.0f;

    // ---- Phase B: survivors only ----
    for (int k = 0; k < total; k++) {
        const int T = sT[k];                            // uniform LDS broadcast
        const int g = sG[k];
        const int t0 = T + 8 * tid;                     // this thread's grain offset
        if (t0 > -8 && t0 < GRAIN_N) {
            const double2 sd = __ldg(sdtab + T);        // uniform, L2-resident
            const double f0s   = __ldg(f0row + g);
            const float  coeff = __ldg(crow + g);

            const double S  = fma(sd.y, Ct, sd.x);      // S(t0)
            const double P  = f0s * S;                  // phase in cycles
            const double fr = P - rint(P);              // [-0.5, 0.5]
            float w   = (float)fr * TWO_PI_F;
            float dlt = (float)(f0s * sd.y * Rt) * TWO_PI_F;  // rad/sample at t0

            const int h  = t0 & 3;                      // == T & 3
            const int jj = ((t0 - h) >> 2) + 2;
            const float4* __restrict__ wt = g_WT + h * WT_N;
            const float4 w40 = __ldg(wt + jj);
            const float4 w41 = __ldg(wt + jj + 1);

            acc[0] = fmaf(__sinf(w) * coeff, w40.x, acc[0]); w += dlt; dlt *= rho;
            acc[1] = fmaf(__sinf(w) * coeff, w40.y, acc[1]); w += dlt; dlt *= rho;
            acc[2] = fmaf(__sinf(w) * coeff, w40.z, acc[2]); w += dlt; dlt *= rho;
            acc[3] = fmaf(__sinf(w) * coeff, w40.w, acc[3]); w += dlt; dlt *= rho;
            acc[4] = fmaf(__sinf(w) * coeff, w41.x, acc[4]); w += dlt; dlt *= rho;
            acc[5] = fmaf(__sinf(w) * coeff, w41.y, acc[5]); w += dlt; dlt *= rho;
            acc[6] = fmaf(__sinf(w) * coeff, w41.z, acc[6]); w += dlt; dlt *= rho;
            acc[7] = fmaf(__sinf(w) * coeff, w41.w, acc[7]);
        }
    }

    // write out (once, coalesced, 32B-aligned per thread)
    float4* __restrict__ o4 =
        (float4*)(out + (size_t)b * N_SAMPLES + r0 + 8 * tid);
    o4[0] = make_float4(acc[0], acc[1], acc[2], acc[3]);
    o4[1] = make_float4(acc[4], acc[5], acc[6], acc[7]);

    // fused norm^2: block partial -> one double atomic per block
    float ss = 0.0f;
    #pragma unroll
    for (int i = 0; i < 8; i++) ss = fmaf(acc[i], acc[i], ss);
    __shared__ float sh[8];
    for (int off = 16; off > 0; off >>= 1)
        ss += __shfl_down_sync(0xFFFFFFFFu, ss, off);
    if ((tid & 31) == 0) sh[tid >> 5] = ss;
    __syncthreads();
    if (tid < 8) {
        ss = sh[tid];
        for (int off = 4; off > 0; off >>= 1)
            ss += __shfl_down_sync(0xFFu, ss, off);
        if (tid == 0) atomicAdd(&g_sum[b], (double)ss);
    }
}

// ============================================================
// Kernel 3: scale by 1/norm. 2048 blocks x 256 threads, 2 float4.
// ============================================================
__global__ void __launch_bounds__(256)
scale_kernel(float4* __restrict__ out4) {
    const int b    = blockIdx.x >> 6;               // 64 blocks per batch
    const int base = blockIdx.x * 512 + threadIdx.x;

    const float inv = rsqrtf((float)g_sum[b]);

    #pragma unroll
    for (int k = 0; k < 2; k++) {
        float4 v = out4[base + 256 * k];
        v.x *= inv; v.y *= inv; v.z *= inv; v.w *= inv;
        out4[base + 256 * k] = v;
    }
}

extern "C" void kernel_launch(void* const* d_in, const int* in_sizes, int n_in,
                              void* d_out, int out_size) {
    const float* theta_d = (const float*)d_in[0];
    const float* theta_s = (const float*)d_in[1];
    const float* u       = (const float*)d_in[2];
    const int*   onsets  = (const int*)d_in[3];
    float* out = (float*)d_out;

    dim3 pgrid(BATCH, 14);
    prep_kernel<<<pgrid, 512>>>(theta_d, theta_s, u);

    synth_kernel<<<BATCH * N_TILES, 256>>>(onsets, out);

    scale_kernel<<<2048, 256>>>((float4*)out);
}

// round 14
// speedup vs baseline: 4.5227x; 1.0066x over previous
#include <cuda_runtime.h>
#include <math.h>

#define SR          44100.0
#define N_SAMPLES   131072
#define N_GRAINS    512
#define GRAIN_N     4096
#define BATCH       32
#define R_TILE      2048      /* output samples per synth block */
#define N_TILES     64        /* N_SAMPLES / R_TILE */
#define TAB_N       6144      /* S/D table entries: T in [-2048, 4096) */
#define LOG2_F0_MIN 8.0f
#define LOG2_F0_MAX 13.0f
#define TYP_SLOPE   14.35546875f  /* 44100/(12*256) */
#define PI_F        3.14159265358979323846f
#define TWO_PI_F    6.28318530717958647692f
#define WT_N        1028      /* float4 entries per shifted window table */

// ---- scratch (no allocations allowed) ----
__device__ double2 g_SD[BATCH * TAB_N];      // {S(T), D(T)} per batch, idx = T+2048
__device__ float  g_cf[BATCH * 8];           // c_i = (rho^i-1)/(rho-1), i=0..7 (fp32)
__device__ double g_c8[BATCH * 256];         // (rho^(8k)-1)/(rho-1)
__device__ double g_R8[BATCH * 256];         // rho^(8k)
__device__ double g_f0s[BATCH * N_GRAINS];   // f0/SR per grain
__device__ float  g_coeff[BATCH * N_GRAINS]; // amp_norm / sqrt(f0)
__device__ float4 g_WT[4 * WT_N];            // shifted zero-padded window, 4-packed
__device__ double g_sum[BATCH];              // ||x||^2 accumulator

// ============================================================
// Kernel 1: prep. grid (32, 14) x 512 threads.
//  part 0      : scalars, c8/R8/cf tables, per-grain quantities
//  part 1..12  : S/D table chunk — ONE exp per entry:
//     D(T) = pref*e^{a(T+1)} = e^{a(T-2047)},  S(T) = (D-pref)/denom
//  part 13     : shifted window tables (b < 4 only)
// ============================================================
__global__ void prep_kernel(const float* __restrict__ theta_d,
                            const float* __restrict__ theta_s,
                            const float* __restrict__ log2_f0_u) {
    const int b    = blockIdx.x;
    const int part = blockIdx.y;
    const int tid  = threadIdx.x;

    const float d     = theta_d[b];
    const float slope = theta_s[b] * 2.0f - 1.0f;
    const float gamma_f = tanf(0.95f * slope * (PI_F * 0.5f)) * TYP_SLOPE * 0.25f;
    const double a = (double)gamma_f * 0.6931471805599453 / SR;

    if (part == 0) {
        if (tid == 0) g_sum[b] = 0.0;
        if (tid < 256) {
            if (a == 0.0) {
                g_c8[b * 256 + tid] = 8.0 * (double)tid;
                g_R8[b * 256 + tid] = 1.0;
            } else {
                g_c8[b * 256 + tid] = expm1(8.0 * a * (double)tid) / expm1(a);
                g_R8[b * 256 + tid] = exp(8.0 * a * (double)tid);
            }
        }
        if (tid >= 256 && tid < 264) {
            const int i = tid - 256;
            g_cf[b * 8 + i] = (a == 0.0) ? (float)i
                            : (float)(expm1(a * (double)i) / expm1(a));
        }
        const float offset = 0.25f * d + 0.75f * d * d;
        const float so0  = (1.0f - d) * (float)N_GRAINS * (0.0f - offset);
        const float amp0 = 1.0f / (1.0f + expf(2.0f * so0));
        const int idx = b * N_GRAINS + tid;
        const float u  = log2_f0_u[idx];
        const float f0 = exp2f(u * (LOG2_F0_MAX - LOG2_F0_MIN) + LOG2_F0_MIN);
        const float so = (1.0f - d) * (float)N_GRAINS * ((float)tid / (float)N_GRAINS - offset);
        const float amp = 1.0f / (1.0f + expf(2.0f * so));
        g_coeff[idx] = (amp / amp0) / sqrtf(f0);
        g_f0s[idx]   = (double)f0 / SR;
    } else if (part <= 12) {
        __shared__ double s_inv, s_pref;
        if (tid == 0) {
            s_pref = (a == 0.0) ? 1.0 : exp(-2048.0 * a);
            s_inv  = (a == 0.0) ? 0.0 : 1.0 / expm1(a);
        }
        __syncthreads();
        const int e = (part - 1) * 512 + tid;   // table index 0..6143
        const int T = e - 2048;
        double S, D;
        if (a == 0.0) {
            S = (double)(T + 1);
            D = 1.0;
        } else {
            D = exp(a * (double)(T - 2047));    // pref*e^{a(T+1)}
            S = (D - s_pref) * s_inv;
        }
        g_SD[b * TAB_N + e] = make_double2(S, D);
    } else {
        if (b < 4) {
            const int h = b;
            for (int jj = tid; jj < WT_N; jj += 512) {
                float4 wv;
                float* wp = (float*)&wv;
                #pragma unroll
                for (int i = 0; i < 4; i++) {
                    const int t = 4 * (jj - 2) + h + i;
                    if (t >= 0 && t < GRAIN_N) {
                        const float w = sinpif((float)t / (float)GRAIN_N);
                        wp[i] = w * w;
                    } else wp[i] = 0.0f;
                }
                g_WT[h * WT_N + jj] = wv;
            }
        }
    }
}

// ============================================================
// Kernel 2: gather synth + fused norm. 2048 blocks x 256 threads.
// Phase A: ordered compaction of grain list (unchanged from R13).
// Phase B: survivors-only loop; per sample the phase is the affine
//  form w_i = w0 + dlt0*c_i (c_i = (rho^i-1)/(rho-1)) — exact
//  closed form of the old serial walk, 3 fma-pipe ops/sample,
//  no loop-carried dependency.
// ============================================================
__global__ void __launch_bounds__(256)
synth_kernel(const int* __restrict__ onsets, float* __restrict__ out) {
    __shared__ int   sT[512];
    __shared__ short sG[512];
    __shared__ int   wcnt[8];

    const int bid  = blockIdx.x;
    const int b    = bid >> 6;
    const int tile = bid & 63;
    const int r0   = tile * R_TILE;
    const int tid  = threadIdx.x;
    const int wid  = tid >> 5, lane = tid & 31;

    const int* __restrict__ ons = onsets + (b << 9);

    // ---- Phase A: ordered compaction ----
    int total = 0;
    #pragma unroll
    for (int p = 0; p < 2; p++) {
        const int g = (p << 8) + tid;
        const int T = r0 - __ldg(ons + g);
        const bool ok = (T > -R_TILE) && (T < GRAIN_N);
        const unsigned m = __ballot_sync(0xFFFFFFFFu, ok);
        if (lane == 0) wcnt[wid] = __popc(m);
        __syncthreads();
        int base = total, all = 0;
        #pragma unroll
        for (int w = 0; w < 8; w++) {
            if (w < wid) base += wcnt[w];
            all += wcnt[w];
        }
        if (ok) {
            const int pos = base + __popc(m & ((1u << lane) - 1));
            sT[pos] = T;
            sG[pos] = (short)g;
        }
        total += all;
        __syncthreads();
    }

    const double Ct = g_c8[b * 256 + tid];   // offset 8*tid from T
    const double Rt = g_R8[b * 256 + tid];   // rho^(8*tid)
    float cf[8];
    #pragma unroll
    for (int i = 0; i < 8; i++) cf[i] = __ldg(g_cf + b * 8 + i);

    const double*  __restrict__ f0row = g_f0s   + (b << 9);
    const float*   __restrict__ crow  = g_coeff + (b << 9);
    const double2* __restrict__ sdtab = g_SD + b * TAB_N + 2048;

    float acc[8];
    #pragma unroll
    for (int i = 0; i < 8; i++) acc[i] = 0.0f;

    // ---- Phase B: survivors only ----
    for (int k = 0; k < total; k++) {
        const int T = sT[k];                            // uniform LDS broadcast
        const int g = sG[k];
        const int t0 = T + 8 * tid;                     // this thread's grain offset
        if (t0 > -8 && t0 < GRAIN_N) {
            const double2 sd = __ldg(sdtab + T);        // uniform, L2-resident
            const double f0s   = __ldg(f0row + g);
            const float  coeff = __ldg(crow + g);

            const double S  = fma(sd.y, Ct, sd.x);      // S(t0)
            const double P  = f0s * S;                  // phase in cycles
            const double fr = P - rint(P);              // [-0.5, 0.5]
            const float w0   = (float)fr * TWO_PI_F;
            const float dlt0 = (float)(f0s * sd.y * Rt) * TWO_PI_F;

            const int h  = t0 & 3;                      // == T & 3
            const int jj = ((t0 - h) >> 2) + 2;
            const float4* __restrict__ wt = g_WT + h * WT_N;
            const float4 w40 = __ldg(wt + jj);
            const float4 w41 = __ldg(wt + jj + 1);

            acc[0] = fmaf(__sinf(fmaf(dlt0, cf[0], w0)) * coeff, w40.x, acc[0]);
            acc[1] = fmaf(__sinf(fmaf(dlt0, cf[1], w0)) * coeff, w40.y, acc[1]);
            acc[2] = fmaf(__sinf(fmaf(dlt0, cf[2], w0)) * coeff, w40.z, acc[2]);
            acc[3] = fmaf(__sinf(fmaf(dlt0, cf[3], w0)) * coeff, w40.w, acc[3]);
            acc[4] = fmaf(__sinf(fmaf(dlt0, cf[4], w0)) * coeff, w41.x, acc[4]);
            acc[5] = fmaf(__sinf(fmaf(dlt0, cf[5], w0)) * coeff, w41.y, acc[5]);
            acc[6] = fmaf(__sinf(fmaf(dlt0, cf[6], w0)) * coeff, w41.z, acc[6]);
            acc[7] = fmaf(__sinf(fmaf(dlt0, cf[7], w0)) * coeff, w41.w, acc[7]);
        }
    }

    // write out (once, coalesced, 32B-aligned per thread)
    float4* __restrict__ o4 =
        (float4*)(out + (size_t)b * N_SAMPLES + r0 + 8 * tid);
    o4[0] = make_float4(acc[0], acc[1], acc[2], acc[3]);
    o4[1] = make_float4(acc[4], acc[5], acc[6], acc[7]);

    // fused norm^2: block partial -> one double atomic per block
    float ss = 0.0f;
    #pragma unroll
    for (int i = 0; i < 8; i++) ss = fmaf(acc[i], acc[i], ss);
    __shared__ float sh[8];
    for (int off = 16; off > 0; off >>= 1)
        ss += __shfl_down_sync(0xFFFFFFFFu, ss, off);
    if ((tid & 31) == 0) sh[tid >> 5] = ss;
    __syncthreads();
    if (tid < 8) {
        ss = sh[tid];
        for (int off = 4; off > 0; off >>= 1)
            ss += __shfl_down_sync(0xFFu, ss, off);
        if (tid == 0) atomicAdd(&g_sum[b], (double)ss);
    }
}

// ============================================================
// Kernel 3: scale by 1/norm. 2048 blocks x 256 threads, 2 float4.
// ============================================================
__global__ void __launch_bounds__(256)
scale_kernel(float4* __restrict__ out4) {
    const int b    = blockIdx.x >> 6;               // 64 blocks per batch
    const int base = blockIdx.x * 512 + threadIdx.x;

    const float inv = rsqrtf((float)g_sum[b]);

    #pragma unroll
    for (int k = 0; k < 2; k++) {
        float4 v = out4[base + 256 * k];
        v.x *= inv; v.y *= inv; v.z *= inv; v.w *= inv;
        out4[base + 256 * k] = v;
    }
}

extern "C" void kernel_launch(void* const* d_in, const int* in_sizes, int n_in,
                              void* d_out, int out_size) {
    const float* theta_d = (const float*)d_in[0];
    const float* theta_s = (const float*)d_in[1];
    const float* u       = (const float*)d_in[2];
    const int*   onsets  = (const int*)d_in[3];
    float* out = (float*)d_out;

    dim3 pgrid(BATCH, 14);
    prep_kernel<<<pgrid, 512>>>(theta_d, theta_s, u);

    synth_kernel<<<BATCH * N_TILES, 256>>>(onsets, out);

    scale_kernel<<<2048, 256>>>((float4*)out);
}

// round 16
// speedup vs baseline: 4.8693x; 1.0766x over previous
#include <cuda_runtime.h>
#include <math.h>

#define SR          44100.0
#define N_SAMPLES   131072
#define N_GRAINS    512
#define GRAIN_N     4096
#define BATCH       32
#define R_TILE      2048      /* output samples per synth block */
#define N_TILES     64        /* N_SAMPLES / R_TILE */
#define TAB_N       6144      /* S/D table entries: T in [-2048, 4096) */
#define LOG2_F0_MIN 8.0f
#define LOG2_F0_MAX 13.0f
#define TYP_SLOPE   14.35546875f  /* 44100/(12*256) */
#define PI_F        3.14159265358979323846f
#define TWO_PI_F    6.28318530717958647692f
#define WT_N        1028      /* float4 entries per shifted window table */

// ---- scratch (no allocations allowed) ----
__device__ double2 g_SD[BATCH * TAB_N];      // {S(T), D(T)} per batch, idx = T+2048
__device__ float  g_cf[BATCH * 8];           // c_i = (rho^i-1)/(rho-1), i=0..7 (fp32)
__device__ double g_c8[BATCH * 256];         // (rho^(8k)-1)/(rho-1)
__device__ double g_R8[BATCH * 256];         // rho^(8k)
__device__ double g_f0s[BATCH * N_GRAINS];   // f0/SR per grain
__device__ float  g_coeff[BATCH * N_GRAINS]; // amp_norm / sqrt(f0)
__device__ float4 g_WT[4 * WT_N];            // shifted zero-padded window, 4-packed
__device__ double g_sum[BATCH];              // ||x||^2 accumulator

// ============================================================
// Kernel 1: prep. grid (32, 14) x 512 threads.
// ============================================================
__global__ void prep_kernel(const float* __restrict__ theta_d,
                            const float* __restrict__ theta_s,
                            const float* __restrict__ log2_f0_u) {
    const int b    = blockIdx.x;
    const int part = blockIdx.y;
    const int tid  = threadIdx.x;

    const float d     = theta_d[b];
    const float slope = theta_s[b] * 2.0f - 1.0f;
    const float gamma_f = tanf(0.95f * slope * (PI_F * 0.5f)) * TYP_SLOPE * 0.25f;
    const double a = (double)gamma_f * 0.6931471805599453 / SR;

    if (part == 0) {
        if (tid == 0) g_sum[b] = 0.0;
        if (tid < 256) {
            if (a == 0.0) {
                g_c8[b * 256 + tid] = 8.0 * (double)tid;
                g_R8[b * 256 + tid] = 1.0;
            } else {
                g_c8[b * 256 + tid] = expm1(8.0 * a * (double)tid) / expm1(a);
                g_R8[b * 256 + tid] = exp(8.0 * a * (double)tid);
            }
        }
        if (tid >= 256 && tid < 264) {
            const int i = tid - 256;
            g_cf[b * 8 + i] = (a == 0.0) ? (float)i
                            : (float)(expm1(a * (double)i) / expm1(a));
        }
        const float offset = 0.25f * d + 0.75f * d * d;
        const float so0  = (1.0f - d) * (float)N_GRAINS * (0.0f - offset);
        const float amp0 = 1.0f / (1.0f + expf(2.0f * so0));
        const int idx = b * N_GRAINS + tid;
        const float u  = log2_f0_u[idx];
        const float f0 = exp2f(u * (LOG2_F0_MAX - LOG2_F0_MIN) + LOG2_F0_MIN);
        const float so = (1.0f - d) * (float)N_GRAINS * ((float)tid / (float)N_GRAINS - offset);
        const float amp = 1.0f / (1.0f + expf(2.0f * so));
        g_coeff[idx] = (amp / amp0) / sqrtf(f0);
        g_f0s[idx]   = (double)f0 / SR;
    } else if (part <= 12) {
        __shared__ double s_inv, s_pref;
        if (tid == 0) {
            s_pref = (a == 0.0) ? 1.0 : exp(-2048.0 * a);
            s_inv  = (a == 0.0) ? 0.0 : 1.0 / expm1(a);
        }
        __syncthreads();
        const int e = (part - 1) * 512 + tid;   // table index 0..6143
        const int T = e - 2048;
        double S, D;
        if (a == 0.0) {
            S = (double)(T + 1);
            D = 1.0;
        } else {
            D = exp(a * (double)(T - 2047));    // pref*e^{a(T+1)}
            S = (D - s_pref) * s_inv;
        }
        g_SD[b * TAB_N + e] = make_double2(S, D);
    } else {
        if (b < 4) {
            const int h = b;
            for (int jj = tid; jj < WT_N; jj += 512) {
                float4 wv;
                float* wp = (float*)&wv;
                #pragma unroll
                for (int i = 0; i < 4; i++) {
                    const int t = 4 * (jj - 2) + h + i;
                    if (t >= 0 && t < GRAIN_N) {
                        const float w = sinpif((float)t / (float)GRAIN_N);
                        wp[i] = w * w;
                    } else wp[i] = 0.0f;
                }
                g_WT[h * WT_N + jj] = wv;
            }
        }
    }
}

// ============================================================
// Kernel 2: gather synth + fused norm. 2048 blocks x 256 threads.
// Phase A: ordered compaction AND param prefetch — the discovering
//  thread loads (S_T, D_T, f0s, coeff) for its survivor with full
//  MLP (up to 512 concurrent scattered loads), stashing in smem.
// Phase B: survivors-only loop touching ONLY smem broadcasts +
//  compute (no global loads on the critical path).
// Accumulation order identical to R13/R14.
// ============================================================
__global__ void __launch_bounds__(256)
synth_kernel(const int* __restrict__ onsets, float* __restrict__ out) {
    __shared__ int    sT[512];
    __shared__ double sS[512];
    __shared__ double sD[512];
    __shared__ double sF[512];
    __shared__ float  sC[512];
    __shared__ int    wcnt[8];

    const int bid  = blockIdx.x;
    const int b    = bid >> 6;
    const int tile = bid & 63;
    const int r0   = tile * R_TILE;
    const int tid  = threadIdx.x;
    const int wid  = tid >> 5, lane = tid & 31;

    const int*     __restrict__ ons   = onsets  + (b << 9);
    const double*  __restrict__ f0row = g_f0s   + (b << 9);
    const float*   __restrict__ crow  = g_coeff + (b << 9);
    const double2* __restrict__ sdtab = g_SD + b * TAB_N + 2048;

    // ---- Phase A: ordered compaction + prefetch ----
    int total = 0;
    #pragma unroll
    for (int p = 0; p < 2; p++) {
        const int g = (p << 8) + tid;
        const int T = r0 - __ldg(ons + g);
        const bool ok = (T > -R_TILE) && (T < GRAIN_N);
        const unsigned m = __ballot_sync(0xFFFFFFFFu, ok);
        if (lane == 0) wcnt[wid] = __popc(m);
        __syncthreads();
        int base = total, all = 0;
        #pragma unroll
        for (int w = 0; w < 8; w++) {
            if (w < wid) base += wcnt[w];
            all += wcnt[w];
        }
        if (ok) {
            const int pos = base + __popc(m & ((1u << lane) - 1));
            sT[pos] = T;
            const double2 sd = __ldg(sdtab + T);    // scattered but parallel
            sS[pos] = sd.x;
            sD[pos] = sd.y;
            sF[pos] = __ldg(f0row + g);
            sC[pos] = __ldg(crow + g);
        }
        total += all;
        __syncthreads();
    }

    const double Ct = g_c8[b * 256 + tid];   // offset 8*tid from T
    const double Rt = g_R8[b * 256 + tid];   // rho^(8*tid)
    float cf[8];
    #pragma unroll
    for (int i = 0; i < 8; i++) cf[i] = __ldg(g_cf + b * 8 + i);

    float acc[8];
    #pragma unroll
    for (int i = 0; i < 8; i++) acc[i] = 0.0f;

    // ---- Phase B: survivors only; smem-only inputs ----
    for (int k = 0; k < total; k++) {
        const int T  = sT[k];                           // uniform LDS broadcast
        const int t0 = T + 8 * tid;                     // this thread's grain offset
        if (t0 > -8 && t0 < GRAIN_N) {
            const double S_T = sS[k];
            const double D_T = sD[k];
            const double f0s = sF[k];
            const float  coeff = sC[k];

            const double S  = fma(D_T, Ct, S_T);        // S(t0)
            const double P  = f0s * S;                  // phase in cycles
            const double fr = P - rint(P);              // [-0.5, 0.5]
            const float w0   = (float)fr * TWO_PI_F;
            const float dlt0 = (float)(f0s * D_T * Rt) * TWO_PI_F;

            const int h  = t0 & 3;                      // == T & 3
            const int jj = ((t0 - h) >> 2) + 2;
            const float4* __restrict__ wt = g_WT + h * WT_N;
            const float4 w40 = __ldg(wt + jj);
            const float4 w41 = __ldg(wt + jj + 1);

            acc[0] = fmaf(__sinf(fmaf(dlt0, cf[0], w0)) * coeff, w40.x, acc[0]);
            acc[1] = fmaf(__sinf(fmaf(dlt0, cf[1], w0)) * coeff, w40.y, acc[1]);
            acc[2] = fmaf(__sinf(fmaf(dlt0, cf[2], w0)) * coeff, w40.z, acc[2]);
            acc[3] = fmaf(__sinf(fmaf(dlt0, cf[3], w0)) * coeff, w40.w, acc[3]);
            acc[4] = fmaf(__sinf(fmaf(dlt0, cf[4], w0)) * coeff, w41.x, acc[4]);
            acc[5] = fmaf(__sinf(fmaf(dlt0, cf[5], w0)) * coeff, w41.y, acc[5]);
            acc[6] = fmaf(__sinf(fmaf(dlt0, cf[6], w0)) * coeff, w41.z, acc[6]);
            acc[7] = fmaf(__sinf(fmaf(dlt0, cf[7], w0)) * coeff, w41.w, acc[7]);
        }
    }

    // write out (once, coalesced, 32B-aligned per thread)
    float4* __restrict__ o4 =
        (float4*)(out + (size_t)b * N_SAMPLES + r0 + 8 * tid);
    o4[0] = make_float4(acc[0], acc[1], acc[2], acc[3]);
    o4[1] = make_float4(acc[4], acc[5], acc[6], acc[7]);

    // fused norm^2: block partial -> one double atomic per block
    float ss = 0.0f;
    #pragma unroll
    for (int i = 0; i < 8; i++) ss = fmaf(acc[i], acc[i], ss);
    __shared__ float sh[8];
    for (int off = 16; off > 0; off >>= 1)
        ss += __shfl_down_sync(0xFFFFFFFFu, ss, off);
    if ((tid & 31) == 0) sh[tid >> 5] = ss;
    __syncthreads();
    if (tid < 8) {
        ss = sh[tid];
        for (int off = 4; off > 0; off >>= 1)
            ss += __shfl_down_sync(0xFFu, ss, off);
        if (tid == 0) atomicAdd(&g_sum[b], (double)ss);
    }
}

// ============================================================
// Kernel 3: scale by 1/norm. 2048 blocks x 256 threads, 2 float4.
// ============================================================
__global__ void __launch_bounds__(256)
scale_kernel(float4* __restrict__ out4) {
    const int b    = blockIdx.x >> 6;               // 64 blocks per batch
    const int base = blockIdx.x * 512 + threadIdx.x;

    const float inv = rsqrtf((float)g_sum[b]);

    #pragma unroll
    for (int k = 0; k < 2; k++) {
        float4 v = out4[base + 256 * k];
        v.x *= inv; v.y *= inv; v.z *= inv; v.w *= inv;
        out4[base + 256 * k] = v;
    }
}

extern "C" void kernel_launch(void* const* d_in, const int* in_sizes, int n_in,
                              void* d_out, int out_size) {
    const float* theta_d = (const float*)d_in[0];
    const float* theta_s = (const float*)d_in[1];
    const float* u       = (const float*)d_in[2];
    const int*   onsets  = (const int*)d_in[3];
    float* out = (float*)d_out;

    dim3 pgrid(BATCH, 14);
    prep_kernel<<<pgrid, 512>>>(theta_d, theta_s, u);

    synth_kernel<<<BATCH * N_TILES, 256>>>(onsets, out);

    scale_kernel<<<2048, 256>>>((float4*)out);
}

// round 17
// speedup vs baseline: 4.9232x; 1.0111x over previous
#include <cuda_runtime.h>
#include <math.h>

#define SR          44100.0
#define N_SAMPLES   131072
#define N_GRAINS    512
#define GRAIN_N     4096
#define BATCH       32
#define R_TILE      2048      /* output samples per synth block */
#define N_TILES     64        /* N_SAMPLES / R_TILE */
#define TAB_N       6144      /* S/D table entries: T in [-2048, 4096) */
#define LOG2_F0_MIN 8.0f
#define LOG2_F0_MAX 13.0f
#define TYP_SLOPE   14.35546875f  /* 44100/(12*256) */
#define PI_F        3.14159265358979323846f
#define TWO_PI_F    6.28318530717958647692f
#define WT_N        1028      /* float4 entries per shifted window table */

// ---- scratch (no allocations allowed) ----
__device__ double2 g_SD[BATCH * TAB_N];      // {S(T), D(T)} per batch, idx = T+2048
__device__ float  g_cf[BATCH * 8];           // c_i = (rho^i-1)/(rho-1), i=0..7 (fp32)
__device__ double g_c8[BATCH * 256];         // (rho^(8k)-1)/(rho-1)
__device__ double g_R8[BATCH * 256];         // rho^(8k)
__device__ double g_f0s[BATCH * N_GRAINS];   // f0/SR per grain
__device__ float  g_coeff[BATCH * N_GRAINS]; // amp_norm / sqrt(f0)
__device__ float4 g_WT[4 * WT_N];            // shifted zero-padded window, 4-packed
__device__ double g_sum[BATCH];              // ||x||^2 accumulator

// ============================================================
// Kernel 1: prep. grid (32, 14) x 512 threads.  (unchanged R16)
// ============================================================
__global__ void prep_kernel(const float* __restrict__ theta_d,
                            const float* __restrict__ theta_s,
                            const float* __restrict__ log2_f0_u) {
    const int b    = blockIdx.x;
    const int part = blockIdx.y;
    const int tid  = threadIdx.x;

    const float d     = theta_d[b];
    const float slope = theta_s[b] * 2.0f - 1.0f;
    const float gamma_f = tanf(0.95f * slope * (PI_F * 0.5f)) * TYP_SLOPE * 0.25f;
    const double a = (double)gamma_f * 0.6931471805599453 / SR;

    if (part == 0) {
        if (tid == 0) g_sum[b] = 0.0;
        if (tid < 256) {
            if (a == 0.0) {
                g_c8[b * 256 + tid] = 8.0 * (double)tid;
                g_R8[b * 256 + tid] = 1.0;
            } else {
                g_c8[b * 256 + tid] = expm1(8.0 * a * (double)tid) / expm1(a);
                g_R8[b * 256 + tid] = exp(8.0 * a * (double)tid);
            }
        }
        if (tid >= 256 && tid < 264) {
            const int i = tid - 256;
            g_cf[b * 8 + i] = (a == 0.0) ? (float)i
                            : (float)(expm1(a * (double)i) / expm1(a));
        }
        const float offset = 0.25f * d + 0.75f * d * d;
        const float so0  = (1.0f - d) * (float)N_GRAINS * (0.0f - offset);
        const float amp0 = 1.0f / (1.0f + expf(2.0f * so0));
        const int idx = b * N_GRAINS + tid;
        const float u  = log2_f0_u[idx];
        const float f0 = exp2f(u * (LOG2_F0_MAX - LOG2_F0_MIN) + LOG2_F0_MIN);
        const float so = (1.0f - d) * (float)N_GRAINS * ((float)tid / (float)N_GRAINS - offset);
        const float amp = 1.0f / (1.0f + expf(2.0f * so));
        g_coeff[idx] = (amp / amp0) / sqrtf(f0);
        g_f0s[idx]   = (double)f0 / SR;
    } else if (part <= 12) {
        __shared__ double s_inv, s_pref;
        if (tid == 0) {
            s_pref = (a == 0.0) ? 1.0 : exp(-2048.0 * a);
            s_inv  = (a == 0.0) ? 0.0 : 1.0 / expm1(a);
        }
        __syncthreads();
        const int e = (part - 1) * 512 + tid;   // table index 0..6143
        const int T = e - 2048;
        double S, D;
        if (a == 0.0) {
            S = (double)(T + 1);
            D = 1.0;
        } else {
            D = exp(a * (double)(T - 2047));    // pref*e^{a(T+1)}
            S = (D - s_pref) * s_inv;
        }
        g_SD[b * TAB_N + e] = make_double2(S, D);
    } else {
        if (b < 4) {
            const int h = b;
            for (int jj = tid; jj < WT_N; jj += 512) {
                float4 wv;
                float* wp = (float*)&wv;
                #pragma unroll
                for (int i = 0; i < 4; i++) {
                    const int t = 4 * (jj - 2) + h + i;
                    if (t >= 0 && t < GRAIN_N) {
                        const float w = sinpif((float)t / (float)GRAIN_N);
                        wp[i] = w * w;
                    } else wp[i] = 0.0f;
                }
                g_WT[h * WT_N + jj] = wv;
            }
        }
    }
}

// ============================================================
// Kernel 2: gather synth + fused norm. 2048 blocks x 256 threads.
// Phase A: ordered compaction + prefetch; per survivor store the
//  PRE-MULTIPLIED products P0 = f0s*S_T, FD = f0s*D_T (two DMULs
//  amortized into the parallel phase) + coeff + short T.
// Phase B: survivors-only, software-pipelined (prefetch k+1's smem
//  params while computing k). Seed chain: DFMA + DRND + DADD only.
// ============================================================
__global__ void __launch_bounds__(256)
synth_kernel(const int* __restrict__ onsets, float* __restrict__ out) {
    __shared__ short  sT[514];     // +pad for pipeline prefetch
    __shared__ double sP0[513];    // f0s * S_T
    __shared__ double sFD[513];    // f0s * D_T
    __shared__ float  sC[513];     // coeff
    __shared__ int    wcnt[8];

    const int bid  = blockIdx.x;
    const int b    = bid >> 6;
    const int tile = bid & 63;
    const int r0   = tile * R_TILE;
    const int tid  = threadIdx.x;
    const int wid  = tid >> 5, lane = tid & 31;

    const int*     __restrict__ ons   = onsets  + (b << 9);
    const double*  __restrict__ f0row = g_f0s   + (b << 9);
    const float*   __restrict__ crow  = g_coeff + (b << 9);
    const double2* __restrict__ sdtab = g_SD + b * TAB_N + 2048;

    // ---- Phase A: ordered compaction + product prefetch ----
    int total = 0;
    #pragma unroll
    for (int p = 0; p < 2; p++) {
        const int g = (p << 8) + tid;
        const int T = r0 - __ldg(ons + g);
        const bool ok = (T > -R_TILE) && (T < GRAIN_N);
        const unsigned m = __ballot_sync(0xFFFFFFFFu, ok);
        if (lane == 0) wcnt[wid] = __popc(m);
        __syncthreads();
        int base = total, all = 0;
        #pragma unroll
        for (int w = 0; w < 8; w++) {
            if (w < wid) base += wcnt[w];
            all += wcnt[w];
        }
        if (ok) {
            const int pos = base + __popc(m & ((1u << lane) - 1));
            const double2 sd = __ldg(sdtab + T);    // scattered but parallel
            const double f0s = __ldg(f0row + g);
            sT[pos]  = (short)T;
            sP0[pos] = f0s * sd.x;
            sFD[pos] = f0s * sd.y;
            sC[pos]  = __ldg(crow + g);
        }
        total += all;
        __syncthreads();
    }

    const double Ct = g_c8[b * 256 + tid];   // offset 8*tid from T
    const double Rt = g_R8[b * 256 + tid];   // rho^(8*tid)
    float cf[8];
    #pragma unroll
    for (int i = 0; i < 8; i++) cf[i] = __ldg(g_cf + b * 8 + i);

    float acc[8];
    #pragma unroll
    for (int i = 0; i < 8; i++) acc[i] = 0.0f;

    // ---- Phase B: survivors only; smem-only inputs, pipelined ----
    int    T_c  = sT[0];
    double P0_c = sP0[0];
    double FD_c = sFD[0];
    float  C_c  = sC[0];

    for (int k = 0; k < total; k++) {
        // prefetch next iteration's params (smem; harmless garbage at k=total)
        const int    T_n  = sT[k + 1];
        const double P0_n = sP0[k + 1];
        const double FD_n = sFD[k + 1];
        const float  C_n  = sC[k + 1];

        const int t0 = T_c + 8 * tid;                   // this thread's grain offset
        if (t0 > -8 && t0 < GRAIN_N) {
            const double P  = fma(FD_c, Ct, P0_c);      // phase in cycles at t0
            const double fr = P - rint(P);              // [-0.5, 0.5]
            const float w0   = (float)fr * TWO_PI_F;
            const float dlt0 = (float)(FD_c * Rt) * TWO_PI_F;

            const int h  = t0 & 3;                      // == T & 3
            const int jj = ((t0 - h) >> 2) + 2;
            const float4* __restrict__ wt = g_WT + h * WT_N;
            const float4 w40 = __ldg(wt + jj);
            const float4 w41 = __ldg(wt + jj + 1);

            acc[0] = fmaf(__sinf(fmaf(dlt0, cf[0], w0)) * C_c, w40.x, acc[0]);
            acc[1] = fmaf(__sinf(fmaf(dlt0, cf[1], w0)) * C_c, w40.y, acc[1]);
            acc[2] = fmaf(__sinf(fmaf(dlt0, cf[2], w0)) * C_c, w40.z, acc[2]);
            acc[3] = fmaf(__sinf(fmaf(dlt0, cf[3], w0)) * C_c, w40.w, acc[3]);
            acc[4] = fmaf(__sinf(fmaf(dlt0, cf[4], w0)) * C_c, w41.x, acc[4]);
            acc[5] = fmaf(__sinf(fmaf(dlt0, cf[5], w0)) * C_c, w41.y, acc[5]);
            acc[6] = fmaf(__sinf(fmaf(dlt0, cf[6], w0)) * C_c, w41.z, acc[6]);
            acc[7] = fmaf(__sinf(fmaf(dlt0, cf[7], w0)) * C_c, w41.w, acc[7]);
        }

        T_c = T_n; P0_c = P0_n; FD_c = FD_n; C_c = C_n;
    }

    // write out (once, coalesced, 32B-aligned per thread)
    float4* __restrict__ o4 =
        (float4*)(out + (size_t)b * N_SAMPLES + r0 + 8 * tid);
    o4[0] = make_float4(acc[0], acc[1], acc[2], acc[3]);
    o4[1] = make_float4(acc[4], acc[5], acc[6], acc[7]);

    // fused norm^2: block partial -> one double atomic per block
    float ss = 0.0f;
    #pragma unroll
    for (int i = 0; i < 8; i++) ss = fmaf(acc[i], acc[i], ss);
    __shared__ float sh[8];
    for (int off = 16; off > 0; off >>= 1)
        ss += __shfl_down_sync(0xFFFFFFFFu, ss, off);
    if ((tid & 31) == 0) sh[tid >> 5] = ss;
    __syncthreads();
    if (tid < 8) {
        ss = sh[tid];
        for (int off = 4; off > 0; off >>= 1)
            ss += __shfl_down_sync(0xFFu, ss, off);
        if (tid == 0) atomicAdd(&g_sum[b], (double)ss);
    }
}

// ============================================================
// Kernel 3: scale by 1/norm. 4096 blocks x 256 threads, 1 float4.
// ============================================================
__global__ void __launch_bounds__(256)
scale_kernel(float4* __restrict__ out4) {
    const int i = blockIdx.x * 256 + threadIdx.x;   // float4 index
    const int b = i >> 15;                          // 32768 float4 per batch

    const float inv = rsqrtf((float)g_sum[b]);

    float4 v = out4[i];
    v.x *= inv; v.y *= inv; v.z *= inv; v.w *= inv;
    out4[i] = v;
}

extern "C" void kernel_launch(void* const* d_in, const int* in_sizes, int n_in,
                              void* d_out, int out_size) {
    const float* theta_d = (const float*)d_in[0];
    const float* theta_s = (const float*)d_in[1];
    const float* u       = (const float*)d_in[2];
    const int*   onsets  = (const int*)d_in[3];
    float* out = (float*)d_out;

    dim3 pgrid(BATCH, 14);
    prep_kernel<<<pgrid, 512>>>(theta_d, theta_s, u);

    synth_kernel<<<BATCH * N_TILES, 256>>>(onsets, out);

    scale_kernel<<<4096, 256>>>((float4*)out);
}